// round 11
// baseline (speedup 1.0000x reference)
#include <cuda_runtime.h>

#define BB 2
#define NN 512
#define DD 512
#define HH 8
#define EE 128
#define MSPLIT 4
#define MCH (NN / MSPLIT)   // 128 m per block
#define PR 8                // bn rows per prep block (parallel, 1 wave)

// Scratch (no cudaMalloc allowed)
__device__ float g_o2[BB * NN * HH];              // 8K floats
__device__ float g_A [(size_t)BB * NN * EE * HH]; // 1M floats = 4 MB

// ---------------------------------------------------------------------------
// Kernel 1: block handles PR=8 bn rows in parallel. Grid 128 -> ONE wave.
//   Phase A: warp h computes o12[bn0+r, h] for r=0..7 (8-way ILP dots, x via L1).
//   Phase B: thread (rb, e) handles rows rb and rb+4: A[e][j] = sum_i o1[i]*W3[e,i*8+j].
// Static smem: 33280 (w3s, pitch 65) + 256 (o1s) = 33.5 KB < 48 KB.
// ---------------------------------------------------------------------------
__global__ void __launch_bounds__(512) prep_kernel(
    const float* __restrict__ x,    // (B,N,D)
    const float* __restrict__ W12,  // (16,D)
    const float* __restrict__ b12,  // (16,)
    const float* __restrict__ W3)   // (E,64)
{
    const int bn0  = blockIdx.x * PR;
    const int tid  = threadIdx.x;       // 512 threads = 16 warps
    const int warp = tid >> 5;          // = h index in phase A
    const int lane = tid & 31;

    __shared__ float w3s[EE * 65];      // pitch 65 -> conflict-free column reads
    __shared__ float o1s[PR][HH];

    // stage W3 (coalesced global read, padded smem write)
    for (int idx = tid; idx < EE * 64; idx += 512) {
        int e = idx >> 6, k = idx & 63;
        w3s[e * 65 + k] = W3[idx];
    }

    // Phase A: warp h computes o12 for 8 rows at once (x through L1: 16 warps
    // in this block read the same 8 rows -> hits after first touch)
    {
        float acc[PR];
        #pragma unroll
        for (int r = 0; r < PR; r++) acc[r] = 0.f;

        const float* w  = W12 + warp * DD;
        const float* xb = x + (size_t)bn0 * DD;
        #pragma unroll 4
        for (int i = lane; i < DD; i += 32) {
            const float wv = __ldg(w + i);
            #pragma unroll
            for (int r = 0; r < PR; r++)
                acc[r] += wv * __ldg(xb + r * DD + i);
        }
        #pragma unroll
        for (int o = 16; o; o >>= 1) {
            #pragma unroll
            for (int r = 0; r < PR; r++)
                acc[r] += __shfl_xor_sync(0xffffffffu, acc[r], o);
        }
        if (lane == 0) {
            const float bb = b12[warp];
            #pragma unroll
            for (int r = 0; r < PR; r++) {
                const float v = acc[r] + bb;
                if (warp < HH) o1s[r][warp] = v;
                else           g_o2[(bn0 + r) * HH + (warp - HH)] = v;
            }
        }
    }
    __syncthreads();

    // Phase B: e = tid&127, rows rb and rb+4; w3 row reused for both rows.
    {
        const int rb = tid >> 7;            // 0..3
        const int e  = tid & 127;
        const float* w3 = w3s + e * 65;     // bank=(e+c)%32: conflict-free

        float a[2][HH];
        #pragma unroll
        for (int s = 0; s < 2; s++)
            #pragma unroll
            for (int j = 0; j < HH; j++) a[s][j] = 0.f;

        #pragma unroll
        for (int i = 0; i < HH; i++) {
            const float w3r[HH] = {w3[i*8+0], w3[i*8+1], w3[i*8+2], w3[i*8+3],
                                   w3[i*8+4], w3[i*8+5], w3[i*8+6], w3[i*8+7]};
            const float o1a = o1s[rb][i];
            const float o1b = o1s[rb + 4][i];
            #pragma unroll
            for (int j = 0; j < HH; j++) {
                a[0][j] += o1a * w3r[j];
                a[1][j] += o1b * w3r[j];
            }
        }
        #pragma unroll
        for (int s = 0; s < 2; s++) {
            float* Ao = g_A + ((size_t)(bn0 + rb + 4 * s) * EE + e) * HH;
            reinterpret_cast<float4*>(Ao)[0] = make_float4(a[s][0], a[s][1], a[s][2], a[s][3]);
            reinterpret_cast<float4*>(Ao)[1] = make_float4(a[s][4], a[s][5], a[s][6], a[s][7]);
        }
    }
}

// ---------------------------------------------------------------------------
// Kernel 2: block per (bn, m-chunk). out[bn,m,e] = b3[e] + sum_j A[bn,e,j]*o2[b,m,j]
// Lane owns an e-QUAD (32 A regs); warp covers all 128 e; per m: 2xLDS.128 +
// 32 FFMA + 1xSTG.128 (0.039 LSU-cyc/B vs 0.062 for the e-pair layout).
// ---------------------------------------------------------------------------
__global__ void __launch_bounds__(256, 4) main_kernel(
    const float* __restrict__ b3,   // (E,)
    float* __restrict__ out)        // (B,N,N,E)
{
    const int bn   = blockIdx.x;
    const int b    = bn >> 9;
    const int mc   = blockIdx.y;
    const int tid  = threadIdx.x;      // 256 = 8 warps
    const int warp = tid >> 5;
    const int lane = tid & 31;

    __shared__ float o2s[MCH * HH];    // 4 KB

    const float4* o2g = reinterpret_cast<const float4*>(
        g_o2 + ((size_t)b * NN + (size_t)mc * MCH) * HH);
    for (int i = tid; i < MCH * HH / 4; i += 256)
        reinterpret_cast<float4*>(o2s)[i] = __ldg(o2g + i);

    // lane's e-quad: e = 4*lane -> 32 A regs
    float a0[HH], a1[HH], a2[HH], a3[HH];
    {
        const float4* Ab = reinterpret_cast<const float4*>(
            g_A + ((size_t)bn * EE + 4 * lane) * HH);
        float4 v;
        v = Ab[0]; a0[0]=v.x; a0[1]=v.y; a0[2]=v.z; a0[3]=v.w;
        v = Ab[1]; a0[4]=v.x; a0[5]=v.y; a0[6]=v.z; a0[7]=v.w;
        v = Ab[2]; a1[0]=v.x; a1[1]=v.y; a1[2]=v.z; a1[3]=v.w;
        v = Ab[3]; a1[4]=v.x; a1[5]=v.y; a1[6]=v.z; a1[7]=v.w;
        v = Ab[4]; a2[0]=v.x; a2[1]=v.y; a2[2]=v.z; a2[3]=v.w;
        v = Ab[5]; a2[4]=v.x; a2[5]=v.y; a2[6]=v.z; a2[7]=v.w;
        v = Ab[6]; a3[0]=v.x; a3[1]=v.y; a3[2]=v.z; a3[3]=v.w;
        v = Ab[7]; a3[4]=v.x; a3[5]=v.y; a3[6]=v.z; a3[7]=v.w;
    }
    const float4 bv = reinterpret_cast<const float4*>(b3)[lane];

    __syncthreads();

    // out as float4: row (bn,m) has EE/4 = 32 float4; lane owns slot lane.
    float4* op = reinterpret_cast<float4*>(out)
               + ((size_t)bn * NN + (size_t)mc * MCH + warp) * (EE / 4) + lane;
    const float4* o2v = reinterpret_cast<const float4*>(o2s) + warp * 2;

    #pragma unroll 4
    for (int it = 0; it < MCH / 8; ++it) {   // m = warp + 8*it
        const float4 p  = o2v[0];
        const float4 qv = o2v[1];

        float4 acc = bv;
        acc.x += a0[0]*p.x;  acc.y += a1[0]*p.x;  acc.z += a2[0]*p.x;  acc.w += a3[0]*p.x;
        acc.x += a0[1]*p.y;  acc.y += a1[1]*p.y;  acc.z += a2[1]*p.y;  acc.w += a3[1]*p.y;
        acc.x += a0[2]*p.z;  acc.y += a1[2]*p.z;  acc.z += a2[2]*p.z;  acc.w += a3[2]*p.z;
        acc.x += a0[3]*p.w;  acc.y += a1[3]*p.w;  acc.z += a2[3]*p.w;  acc.w += a3[3]*p.w;
        acc.x += a0[4]*qv.x; acc.y += a1[4]*qv.x; acc.z += a2[4]*qv.x; acc.w += a3[4]*qv.x;
        acc.x += a0[5]*qv.y; acc.y += a1[5]*qv.y; acc.z += a2[5]*qv.y; acc.w += a3[5]*qv.y;
        acc.x += a0[6]*qv.z; acc.y += a1[6]*qv.z; acc.z += a2[6]*qv.z; acc.w += a3[6]*qv.z;
        acc.x += a0[7]*qv.w; acc.y += a1[7]*qv.w; acc.z += a2[7]*qv.w; acc.w += a3[7]*qv.w;

        __stcs(op, acc);
        op  += 8 * (EE / 4);   // next m (stride 8)
        o2v += 8 * 2;
    }
}

extern "C" void kernel_launch(void* const* d_in, const int* in_sizes, int n_in,
                              void* d_out, int out_size)
{
    const float* x   = (const float*)d_in[0];
    const float* W12 = (const float*)d_in[1];
    const float* b12 = (const float*)d_in[2];
    const float* W3  = (const float*)d_in[3];
    const float* b3  = (const float*)d_in[4];
    float* out = (float*)d_out;

    prep_kernel<<<BB * NN / PR, 512>>>(x, W12, b12, W3);
    main_kernel<<<dim3(BB * NN, MSPLIT), 256>>>(b3, out);
}

// round 12
// speedup vs baseline: 1.1692x; 1.1692x over previous
#include <cuda_runtime.h>

#define BB 2
#define NN 512
#define DD 512
#define HH 8
#define EE 128
#define MSPLIT 4
#define MCH (NN / MSPLIT)   // 128 m per block
#define PR 4                // bn rows per prep block, processed in PARALLEL
#define TM 32               // m rows per output tile (16 KB)

// Scratch (no cudaMalloc allowed)
__device__ float g_o2[BB * NN * HH];              // 8K floats
__device__ float g_A [(size_t)BB * NN * EE * HH]; // 1M floats = 4 MB

// ---------------------------------------------------------------------------
// Kernel 1 (R10 design): block handles PR=4 bn rows in parallel.
//   Phase A: warp h computes o12[bn0+r, h] for r=0..3 (4 ILP dot products).
//   Phase B: all 512 threads: (r, e) -> A[e][j] = sum_i o1[i]*W3[e, i*8+j].
// Static smem: 33280 (w3s) + 8192 (xs) + 128 (o1s) = 41.6 KB < 48 KB.
// ---------------------------------------------------------------------------
__global__ void __launch_bounds__(512) prep_kernel(
    const float* __restrict__ x,    // (B,N,D)
    const float* __restrict__ W12,  // (16,D)
    const float* __restrict__ b12,  // (16,)
    const float* __restrict__ W3)   // (E,64)
{
    const int bn0  = blockIdx.x * PR;
    const int tid  = threadIdx.x;       // 512 threads = 16 warps
    const int warp = tid >> 5;          // = h index in phase A
    const int lane = tid & 31;

    __shared__ float w3s[EE * 65];      // pitch 65 -> conflict-free column reads
    __shared__ float xs[PR * DD];
    __shared__ float o1s[PR][HH];

    for (int idx = tid; idx < EE * 64; idx += 512) {
        int e = idx >> 6, k = idx & 63;
        w3s[e * 65 + k] = W3[idx];
    }
    {
        const float4* xg = reinterpret_cast<const float4*>(x + (size_t)bn0 * DD);
        for (int i = tid; i < PR * DD / 4; i += 512)
            reinterpret_cast<float4*>(xs)[i] = __ldg(xg + i);
    }
    __syncthreads();

    // Phase A: warp h, 4 rows at once (W12 row reused, 4-way ILP)
    {
        float a0 = 0.f, a1 = 0.f, a2 = 0.f, a3 = 0.f;
        const float* w = W12 + warp * DD;
        #pragma unroll 4
        for (int i = lane; i < DD; i += 32) {
            const float wv = __ldg(w + i);
            a0 += wv * xs[0 * DD + i];
            a1 += wv * xs[1 * DD + i];
            a2 += wv * xs[2 * DD + i];
            a3 += wv * xs[3 * DD + i];
        }
        #pragma unroll
        for (int o = 16; o; o >>= 1) {
            a0 += __shfl_xor_sync(0xffffffffu, a0, o);
            a1 += __shfl_xor_sync(0xffffffffu, a1, o);
            a2 += __shfl_xor_sync(0xffffffffu, a2, o);
            a3 += __shfl_xor_sync(0xffffffffu, a3, o);
        }
        if (lane == 0) {
            const float bb = b12[warp];
            float v[PR] = {a0 + bb, a1 + bb, a2 + bb, a3 + bb};
            #pragma unroll
            for (int r = 0; r < PR; r++) {
                if (warp < HH) o1s[r][warp] = v[r];
                else           g_o2[(bn0 + r) * HH + (warp - HH)] = v[r];
            }
        }
    }
    __syncthreads();

    // Phase B: all threads. r = tid/128, e = tid%128.
    {
        const int r = tid >> 7;
        const int e = tid & 127;

        float o1r[HH];
        #pragma unroll
        for (int i = 0; i < HH; i++) o1r[i] = o1s[r][i];   // smem broadcast

        const float* w3 = w3s + e * 65;     // bank=(e+c)%32: conflict-free
        float a[HH];
        #pragma unroll
        for (int j = 0; j < HH; j++) a[j] = 0.f;
        #pragma unroll
        for (int i = 0; i < HH; i++) {
            #pragma unroll
            for (int j = 0; j < HH; j++)
                a[j] += o1r[i] * w3[i * HH + j];
        }
        float* Ao = g_A + ((size_t)(bn0 + r) * EE + e) * HH;
        reinterpret_cast<float4*>(Ao)[0] = make_float4(a[0], a[1], a[2], a[3]);
        reinterpret_cast<float4*>(Ao)[1] = make_float4(a[4], a[5], a[6], a[7]);
    }
}

// ---------------------------------------------------------------------------
// Kernel 2: block per (bn, m-chunk). out[bn,m,e] = b3[e] + sum_j A[bn,e,j]*o2[b,m,j]
// e-PAIR per lane (16 A regs, ~40 regs total -> 75% occ). Results go to smem
// tiles (32 m x 128 e = 16 KB, double-buffered) and are flushed to GMEM by the
// TMA async proxy (cp.async.bulk) -- gmem stores leave the per-SM LSU entirely.
// ---------------------------------------------------------------------------
__global__ void __launch_bounds__(256, 6) main_kernel(
    const float* __restrict__ b3,   // (E,)
    float* __restrict__ out)        // (B,N,N,E)
{
    const int bn   = blockIdx.x;
    const int b    = bn >> 9;
    const int mc   = blockIdx.y;
    const int tid  = threadIdx.x;      // 256 = 8 warps
    const int warp = tid >> 5;
    const int lane = tid & 31;

    __shared__ float o2s[MCH * HH];                       // 4 KB
    __shared__ __align__(16) float obuf[2][TM * EE];      // 2 x 16 KB

    const float4* o2g = reinterpret_cast<const float4*>(
        g_o2 + ((size_t)b * NN + (size_t)mc * MCH) * HH);
    for (int i = tid; i < MCH * HH / 4; i += 256)
        reinterpret_cast<float4*>(o2s)[i] = __ldg(o2g + i);

    // lane's e-pair: e = 64*(warp&1) + 2*lane  -> 16 A regs
    const int ebase = ((warp & 1) << 6) + (lane << 1);
    float a0[HH], a1[HH];
    {
        const float4* Ab = reinterpret_cast<const float4*>(
            g_A + ((size_t)bn * EE + ebase) * HH);
        float4 v0 = Ab[0], v1 = Ab[1], v2 = Ab[2], v3 = Ab[3];
        a0[0]=v0.x; a0[1]=v0.y; a0[2]=v0.z; a0[3]=v0.w;
        a0[4]=v1.x; a0[5]=v1.y; a0[6]=v1.z; a0[7]=v1.w;
        a1[0]=v2.x; a1[1]=v2.y; a1[2]=v2.z; a1[3]=v2.w;
        a1[4]=v3.x; a1[5]=v3.y; a1[6]=v3.z; a1[7]=v3.w;
    }
    const float2 bv = reinterpret_cast<const float2*>(b3)[ebase >> 1];

    __syncthreads();

    const int mrow = warp >> 1;        // 0..3 within a tile stride-4 sweep
    float* gbase = out + ((size_t)bn * NN + (size_t)mc * MCH) * EE;

    #pragma unroll
    for (int t = 0; t < MCH / TM; ++t) {          // 4 tiles of 32 m
        if (t >= 2) {                              // buffer t&1 must be drained
            if (tid == 0)
                asm volatile("cp.async.bulk.wait_group.read 1;" ::: "memory");
            __syncthreads();
        }
        float* buf = obuf[t & 1];
        const float* o2t = o2s + (t * TM) * HH;

        #pragma unroll
        for (int k = 0; k < TM / 4; ++k) {         // row = mrow + 4k
            const int row = mrow + 4 * k;
            const float4 p  = reinterpret_cast<const float4*>(o2t + row * HH)[0];
            const float4 qv = reinterpret_cast<const float4*>(o2t + row * HH)[1];

            float ax = bv.x, ay = bv.y;
            ax += a0[0]*p.x;  ay += a1[0]*p.x;
            ax += a0[1]*p.y;  ay += a1[1]*p.y;
            ax += a0[2]*p.z;  ay += a1[2]*p.z;
            ax += a0[3]*p.w;  ay += a1[3]*p.w;
            ax += a0[4]*qv.x; ay += a1[4]*qv.x;
            ax += a0[5]*qv.y; ay += a1[5]*qv.y;
            ax += a0[6]*qv.z; ay += a1[6]*qv.z;
            ax += a0[7]*qv.w; ay += a1[7]*qv.w;

            reinterpret_cast<float2*>(buf + row * EE)[ebase >> 1] =
                make_float2(ax, ay);
        }
        __syncthreads();                           // tile complete (drains STS)

        if (tid == 0) {
            asm volatile("fence.proxy.async.shared::cta;" ::: "memory");
            unsigned saddr = (unsigned)__cvta_generic_to_shared(buf);
            asm volatile(
                "cp.async.bulk.global.shared::cta.bulk_group [%0], [%1], %2;"
                :: "l"(gbase + (size_t)t * TM * EE), "r"(saddr),
                   "r"((unsigned)(TM * EE * 4))
                : "memory");
            asm volatile("cp.async.bulk.commit_group;" ::: "memory");
        }
    }
    if (tid == 0)
        asm volatile("cp.async.bulk.wait_group 0;" ::: "memory");
}

extern "C" void kernel_launch(void* const* d_in, const int* in_sizes, int n_in,
                              void* d_out, int out_size)
{
    const float* x   = (const float*)d_in[0];
    const float* W12 = (const float*)d_in[1];
    const float* b12 = (const float*)d_in[2];
    const float* W3  = (const float*)d_in[3];
    const float* b3  = (const float*)d_in[4];
    float* out = (float*)d_out;

    prep_kernel<<<BB * NN / PR, 512>>>(x, W12, b12, W3);
    main_kernel<<<dim3(BB * NN, MSPLIT), 256>>>(b3, out);
}